// round 8
// baseline (speedup 1.0000x reference)
#include <cuda_runtime.h>

#define NB 26
#define POSE_F 78        // 26*3 floats per pose
#define PPB 32           // poses per block
#define TPB 96           // 3 warps: spine / chains-A / chains-B
#define BATCH 131072

#define TAB_F (NB * 5 + NB * 3)   // 130 rr5 entries + 78 rel_loc = 208

// Staging global filled by the pre-kernel, then copied once into __constant__.
__device__ float g_tab[TAB_F];
__constant__ float c_tab[TAB_F];

#define C_RR5(i) c_tab[(i)]
#define C_RL(i)  c_tab[NB * 5 + (i)]

struct M3 { float a[9]; };
struct V3 { float v[3]; };

__device__ __forceinline__ float fsqrt_approx(float t) {
    t = fmaxf(t, 1e-30f);
    return t * rsqrtf(t);
}

// Full bone step: abs_loc + rotation chain update. Ap/bp by value (aliasing OK).
__device__ __forceinline__ void fullstep(int bone, M3 Ap, V3 bp, M3& Ao, V3& bo,
                                         float* __restrict__ P)
{
    const float lx = C_RL(bone * 3 + 0);
    const float ly = C_RL(bone * 3 + 1);
    const float lz = C_RL(bone * 3 + 2);

    float ax = lx * Ap.a[0] + ly * Ap.a[3] + lz * Ap.a[6] + bp.v[0];
    float ay = lx * Ap.a[1] + ly * Ap.a[4] + lz * Ap.a[7] + bp.v[1];
    float az = lx * Ap.a[2] + ly * Ap.a[5] + lz * Ap.a[8] + bp.v[2];

    float ez = P[bone * 3 + 0];
    float ey = P[bone * 3 + 1];
    float ex = P[bone * 3 + 2];
    P[bone * 3 + 0] = ax;
    P[bone * 3 + 1] = ay;
    P[bone * 3 + 2] = az;

    float sz, cz, sy, cy, sx, cx;
    __sincosf(ez, &sz, &cz);
    __sincosf(ey, &sy, &cy);
    __sincosf(ex, &sx, &cx);

    // Only 5 entries of M = R_ref (hadamard) R_chg feed matrix_to_euler.
    float M00 = C_RR5(bone * 5 + 0) * (cz * cy);
    float M10 = C_RR5(bone * 5 + 1) * (sz * cy);
    float M20 = C_RR5(bone * 5 + 2) * (-sy);
    float M21 = C_RR5(bone * 5 + 3) * (cy * sx);
    float M22 = C_RR5(bone * 5 + 4) * (cy * cx);

    // Trig-free euler->matrix rebuild.
    float i0 = rsqrtf(fmaxf(M00 * M00 + M10 * M10, 1e-30f));
    float CZ = M00 * i0, SZ = M10 * i0;
    float SY = -M20;
    float CY = fsqrt_approx(1.0f - SY * SY);
    float i2 = rsqrtf(fmaxf(M21 * M21 + M22 * M22, 1e-30f));
    float CX = M22 * i2, SX = M21 * i2;

    float R00 = CZ * CY;
    float R01 = CZ * SY * SX - SZ * CX;
    float R02 = CZ * SY * CX + SZ * SX;
    float R10 = SZ * CY;
    float R11 = SZ * SY * SX + CZ * CX;
    float R12 = SZ * SY * CX - CZ * SX;
    float R20 = -SY;
    float R21 = CY * SX;
    float R22 = CY * CX;

    M3 T;
    #pragma unroll
    for (int k = 0; k < 3; k++) {
        float a0 = Ap.a[3 * k + 0], a1 = Ap.a[3 * k + 1], a2 = Ap.a[3 * k + 2];
        T.a[3 * k + 0] = a0 * R00 + a1 * R10 + a2 * R20;
        T.a[3 * k + 1] = a0 * R01 + a1 * R11 + a2 * R21;
        T.a[3 * k + 2] = a0 * R02 + a1 * R12 + a2 * R22;
    }
    float tx = bp.v[0] + lx, ty = bp.v[1] + ly, tz = bp.v[2] + lz;
    V3 tb;
    tb.v[0] = tx * R00 + ty * R10 + tz * R20;
    tb.v[1] = tx * R01 + ty * R11 + tz * R21;
    tb.v[2] = tx * R02 + ty * R12 + tz * R22;

    Ao = T;
    bo = tb;
}

__device__ __forceinline__ void leafstep(int bone, const M3& Ap, const V3& bp,
                                         float* __restrict__ P)
{
    const float lx = C_RL(bone * 3 + 0);
    const float ly = C_RL(bone * 3 + 1);
    const float lz = C_RL(bone * 3 + 2);
    P[bone * 3 + 0] = lx * Ap.a[0] + ly * Ap.a[3] + lz * Ap.a[6] + bp.v[0];
    P[bone * 3 + 1] = lx * Ap.a[1] + ly * Ap.a[4] + lz * Ap.a[7] + bp.v[1];
    P[bone * 3 + 2] = lx * Ap.a[2] + ly * Ap.a[5] + lz * Ap.a[8] + bp.v[2];
}

// Pre-kernel: accurate trig once for the 26 reference rotations + rel_loc copy.
__global__ void ref_table_kernel(const float* __restrict__ rel_rot_ref,
                                 const float* __restrict__ rel_loc)
{
    int i = threadIdx.x;
    if (i < NB) {
        float ez = rel_rot_ref[i * 3 + 0];
        float ey = rel_rot_ref[i * 3 + 1];
        float ex = rel_rot_ref[i * 3 + 2];
        float sz, cz, sy, cy, sx, cx;
        sincosf(ez, &sz, &cz);
        sincosf(ey, &sy, &cy);
        sincosf(ex, &sx, &cx);
        g_tab[i * 5 + 0] = cz * cy;
        g_tab[i * 5 + 1] = sz * cy;
        g_tab[i * 5 + 2] = -sy;
        g_tab[i * 5 + 3] = cy * sx;
        g_tab[i * 5 + 4] = cy * cx;
    }
    for (int j = i; j < NB * 3; j += blockDim.x)
        g_tab[NB * 5 + j] = rel_loc[j];
}

__global__ void __launch_bounds__(TPB, 11)
fk_kernel(const float* __restrict__ x,
          float* __restrict__ out)
{
    __shared__ float pose[PPB * POSE_F];     // 9984 B, in-place angles->abs_loc
    // Published spine states, k-major for conflict-free access:
    // st[k*32 + p]: k 0-8 = A1, 9-11 = b1, 12-20 = A4, 21-23 = b4
    __shared__ float st[24 * PPB];

    const int tid  = threadIdx.x;
    const int warp = tid >> 5;
    const int lane = tid & 31;

    // Coalesced float4 staging: 624 float4s over 96 threads, 7 iters (last partial).
    const int NV4 = PPB * POSE_F / 4;                 // 624
    const int NIT = (NV4 + TPB - 1) / TPB;            // 7
    const float4* gin = reinterpret_cast<const float4*>(x) + (size_t)blockIdx.x * NV4;
    float4* sp4 = reinterpret_cast<float4*>(pose);
    #pragma unroll
    for (int i = 0; i < NIT; i++) {
        int idx = tid + i * TPB;
        if (idx < NV4) sp4[idx] = gin[idx];
    }
    __syncthreads();

    float* P = pose + lane * POSE_F;   // every warp covers all 32 poses, lane = pose

    M3 A; V3 b;

    // ---- Phase 1: warp0 runs bones 0,1 and publishes A1/b1 ----
    if (warp == 0) {
        M3 I; V3 z;
        I.a[0] = 1.f; I.a[1] = 0.f; I.a[2] = 0.f;
        I.a[3] = 0.f; I.a[4] = 1.f; I.a[5] = 0.f;
        I.a[6] = 0.f; I.a[7] = 0.f; I.a[8] = 1.f;
        z.v[0] = 0.f; z.v[1] = 0.f; z.v[2] = 0.f;
        fullstep(0, I, z, A, b, P);
        fullstep(1, A, b, A, b, P);
        #pragma unroll
        for (int k = 0; k < 9; k++) st[k * PPB + lane] = A.a[k];
        #pragma unroll
        for (int k = 0; k < 3; k++) st[(9 + k) * PPB + lane] = b.v[k];
    }
    __syncthreads();   // A1/b1 published

    // ---- Phase 2: warp0 spine 2,3,4 (publish A4/b4); warp1/2 A1-chains ----
    if (warp == 0) {
        fullstep(2, A, b, A, b, P);
        fullstep(3, A, b, A, b, P);
        fullstep(4, A, b, A, b, P);
        #pragma unroll
        for (int k = 0; k < 9; k++) st[(12 + k) * PPB + lane] = A.a[k];
        #pragma unroll
        for (int k = 0; k < 3; k++) st[(21 + k) * PPB + lane] = b.v[k];
    } else {
        #pragma unroll
        for (int k = 0; k < 9; k++) A.a[k] = st[k * PPB + lane];
        #pragma unroll
        for (int k = 0; k < 3; k++) b.v[k] = st[(9 + k) * PPB + lane];
        if (warp == 1) {
            fullstep(15, A, b, A, b, P);
            fullstep(16, A, b, A, b, P);
            fullstep(17, A, b, A, b, P);
            leafstep(18, A, b, P);
        } else {
            fullstep(19, A, b, A, b, P);
            fullstep(20, A, b, A, b, P);
            fullstep(21, A, b, A, b, P);
            leafstep(22, A, b, P);
        }
    }
    __syncthreads();   // A4/b4 published

    // ---- Phase 3: warp0 spine 5,6 + head leaves; warp1/2 A4-chains ----
    if (warp == 0) {
        fullstep(5, A, b, A, b, P);
        fullstep(6, A, b, A, b, P);
        leafstep(23, A, b, P);
        leafstep(24, A, b, P);
        leafstep(25, A, b, P);
    } else {
        #pragma unroll
        for (int k = 0; k < 9; k++) A.a[k] = st[(12 + k) * PPB + lane];
        #pragma unroll
        for (int k = 0; k < 3; k++) b.v[k] = st[(21 + k) * PPB + lane];
        if (warp == 1) {
            fullstep(7, A, b, A, b, P);
            fullstep(8, A, b, A, b, P);
            fullstep(9, A, b, A, b, P);
            leafstep(10, A, b, P);
        } else {
            fullstep(11, A, b, A, b, P);
            fullstep(12, A, b, A, b, P);
            fullstep(13, A, b, A, b, P);
            leafstep(14, A, b, P);
        }
    }
    __syncthreads();

    // Coalesced float4 write-back
    float4* gout = reinterpret_cast<float4*>(out) + (size_t)blockIdx.x * NV4;
    #pragma unroll
    for (int i = 0; i < NIT; i++) {
        int idx = tid + i * TPB;
        if (idx < NV4) gout[idx] = sp4[idx];
    }
}

extern "C" void kernel_launch(void* const* d_in, const int* in_sizes, int n_in,
                              void* d_out, int out_size)
{
    const float* x           = (const float*)d_in[0];  // (131072, 26, 3)
    const float* rel_loc     = (const float*)d_in[1];  // (26, 3)
    const float* rel_rot_ref = (const float*)d_in[2];  // (26, 3)
    float* out               = (float*)d_out;          // (131072, 26, 3)

    const int batch = in_sizes[0] / POSE_F;            // 131072

    ref_table_kernel<<<1, 128>>>(rel_rot_ref, rel_loc);

    void* g_tab_ptr = nullptr;
    cudaGetSymbolAddress(&g_tab_ptr, g_tab);
    cudaMemcpyToSymbolAsync(c_tab, g_tab_ptr, sizeof(float) * TAB_F, 0,
                            cudaMemcpyDeviceToDevice, 0);

    fk_kernel<<<batch / PPB, TPB>>>(x, out);
}